// round 13
// baseline (speedup 1.0000x reference)
#include <cuda_runtime.h>
#include <cuda_bf16.h>
#include <cuda_fp16.h>
#include <mma.h>
#include <math.h>
#include <stdint.h>

using namespace nvcuda;

#define MAXN 4096
#define D    128

// ---------------- scratch (device globals; no allocation allowed) -------------
__device__ __half        g_S[(size_t)MAXN * MAXN]; // exp(sim/tau) in fp16, masked = 0
__device__ __nv_bfloat16 g_hn[MAXN * D];           // normalized hard_neg rows (bf16)
__device__ float         g_pos[MAXN];              // exp(cos(hp_x, hp_qx)/tau)
__device__ float         g_loss[MAXN];
__device__ int           g_q[MAXN];                // positive-pair partner

// ---------------- K0: build partner map ---------------------------------------
__global__ void build_q_kernel(const int* __restrict__ pp, int npairs) {
    int r = blockIdx.x * blockDim.x + threadIdx.x;
    if (r < npairs) g_q[pp[2 * r]] = pp[2 * r + 1];
}

// ---------------- K1: normalized hard_neg rows (bf16) + pos --------------------
__global__ void prep_kernel(const float* __restrict__ emb, int N) {
    int x = blockIdx.x;
    int d = threadIdx.x;
    int qx = g_q[x];
    int fx = N - 1;
    while (fx == x || fx == qx) fx--;   // largest index not in {x, q[x]}

    float a  = emb[(size_t)x  * D + d];
    float b  = emb[(size_t)qx * D + d];
    float pf = emb[(size_t)fx * D + d];
    float h  = 0.5f * (a + pf);

    float v0 = h * h, v1 = a * a, v2 = b * b, v3 = a * b;
    __shared__ float sh[4][4];
    int lane = d & 31, w = d >> 5;
    #pragma unroll
    for (int o = 16; o; o >>= 1) {
        v0 += __shfl_xor_sync(0xffffffffu, v0, o);
        v1 += __shfl_xor_sync(0xffffffffu, v1, o);
        v2 += __shfl_xor_sync(0xffffffffu, v2, o);
        v3 += __shfl_xor_sync(0xffffffffu, v3, o);
    }
    if (lane == 0) { sh[0][w] = v0; sh[1][w] = v1; sh[2][w] = v2; sh[3][w] = v3; }
    __syncthreads();
    float nn = sh[0][0] + sh[0][1] + sh[0][2] + sh[0][3];
    float inv = 1.0f / fmaxf(sqrtf(nn), 1e-8f);
    g_hn[(size_t)x * D + d] = __float2bfloat16(h * inv);

    if (d == 0) {
        float aa = sh[1][0] + sh[1][1] + sh[1][2] + sh[1][3];
        float bb = sh[2][0] + sh[2][1] + sh[2][2] + sh[2][3];
        float ab = sh[3][0] + sh[3][1] + sh[3][2] + sh[3][3];
        float dot = 2.5f * ab - 0.75f * (aa + bb);
        float nxx = 2.25f * aa + 0.25f * bb - 1.5f * ab;
        float nyy = 2.25f * bb + 0.25f * aa - 1.5f * ab;
        float nx = fmaxf(sqrtf(nxx), 1e-8f);
        float ny = fmaxf(sqrtf(nyy), 1e-8f);
        g_pos[x] = expf((dot / (nx * ny)) * 5.0f);
    }
}

// ---------------- K2: WMMA bf16 GEMM + exp + mask (fp16 out, TRIANGLE) ---------
// 128x128 tile per CTA, upper triangle only (528 CTAs), mirror store.
// Full K=128 resident (KP=136 bf16 = 272B stride, ldmatrix conflict-free).
// Inner loop keeps ONE b-fragment live -> no spills at 2 CTAs/SM.
#define KPn 136
#define TSZn (128 * KPn)     // bf16 elements per tile (34816 B)
#define LDS 132              // staging row stride (floats); 528B = 33*16B -> legal

__global__ void __launch_bounds__(256, 2) gemm_wmma_kernel(int N) {
    extern __shared__ char smem[];
    __nv_bfloat16* Ah = (__nv_bfloat16*)smem;
    __nv_bfloat16* Bh = Ah + TSZn;
    float* Tst = (float*)smem;          // epilogue staging 128 x LDS (reuses tiles)
    __shared__ int s_qa[128];           // q[m0 + r]
    __shared__ int s_qb[128];           // q[n0 + c]

    int nb = N >> 7;
    int bid = blockIdx.x;
    int bi = 0, rem = bid;
    while (rem >= nb - bi) { rem -= nb - bi; bi++; }
    int bj = bi + rem;                  // bj >= bi
    int m0 = bi * 128, n0 = bj * 128;

    int tid = threadIdx.x, wid = tid >> 5;
    int wm = wid >> 1, wn = wid & 1;    // warp tile: rows wm*32..+32, cols wn*64..+64

    if (tid < 128)      s_qa[tid]       = g_q[m0 + tid];
    else                s_qb[tid - 128] = g_q[n0 + (tid - 128)];

    wmma::fragment<wmma::accumulator, 16, 16, 16, float> acc[2][4];
    #pragma unroll
    for (int i = 0; i < 2; ++i)
        #pragma unroll
        for (int j = 0; j < 4; ++j) wmma::fill_fragment(acc[i][j], 0.0f);

    // load both full-K tiles (128 rows x 128 bf16 = 16 uint4/row)
    {
        const __nv_bfloat16* srcA = g_hn + (size_t)bi * 128 * D;
        const __nv_bfloat16* srcB = g_hn + (size_t)bj * 128 * D;
        #pragma unroll
        for (int i = tid; i < 2048; i += 256) {
            int row = i >> 4, c8 = i & 15;
            *(uint4*)(Ah + row * KPn + c8 * 8) = *(const uint4*)(srcA + (size_t)row * D + c8 * 8);
            *(uint4*)(Bh + row * KPn + c8 * 8) = *(const uint4*)(srcB + (size_t)row * D + c8 * 8);
        }
    }
    __syncthreads();

    #pragma unroll
    for (int ks = 0; ks < 8; ++ks) {
        wmma::fragment<wmma::matrix_a, 16, 16, 16, __nv_bfloat16, wmma::row_major> a_f[2];
        #pragma unroll
        for (int i = 0; i < 2; ++i)
            wmma::load_matrix_sync(a_f[i], Ah + (wm * 32 + i * 16) * KPn + ks * 16, KPn);
        #pragma unroll
        for (int j = 0; j < 4; ++j) {
            wmma::fragment<wmma::matrix_b, 16, 16, 16, __nv_bfloat16, wmma::col_major> b_f;
            wmma::load_matrix_sync(b_f, Bh + (wn * 64 + j * 16) * KPn + ks * 16, KPn);
            wmma::mma_sync(acc[0][j], a_f[0], b_f, acc[0][j]);
            wmma::mma_sync(acc[1][j], a_f[1], b_f, acc[1][j]);
        }
    }
    __syncthreads();

    // stage raw accumulators to smem (ldm = 132 floats = 528B, multiple of 16B)
    #pragma unroll
    for (int i = 0; i < 2; ++i)
        #pragma unroll
        for (int j = 0; j < 4; ++j)
            wmma::store_matrix_sync(Tst + (wm * 32 + i * 16) * LDS + wn * 64 + j * 16,
                                    acc[i][j], LDS, wmma::mem_row_major);
    __syncthreads();

    // direct store: thread -> 8 consecutive cols of one row; fused mask+exp; STG.128
    {
        int rbase = tid >> 4;            // 0..15
        int c8 = (tid & 15) * 8;         // 0,8,..,120
        #pragma unroll
        for (int p = 0; p < 8; ++p) {
            int r = p * 16 + rbase;
            int m = m0 + r, qm = s_qa[r];
            const float* src = Tst + r * LDS + c8;
            unsigned pkw[4];
            #pragma unroll
            for (int h2 = 0; h2 < 4; ++h2) {
                int n_a = n0 + c8 + 2 * h2, n_b = n_a + 1;
                float fa = (n_a == m || n_a == qm) ? 0.0f : __expf(src[2 * h2]     * 5.0f);
                float fb = (n_b == m || n_b == qm) ? 0.0f : __expf(src[2 * h2 + 1] * 5.0f);
                __half2 hh = __floats2half2_rn(fa, fb);
                pkw[h2] = *(unsigned*)&hh;
            }
            *(uint4*)(g_S + (size_t)m * N + n0 + c8) =
                make_uint4(pkw[0], pkw[1], pkw[2], pkw[3]);
        }
    }
    // mirror store: thread owns staging column c; gathers 8 rows; fused mask+exp
    {
        int c    = tid & 127;
        int hseg = tid >> 7;             // 0/1 -> r halves
        int nrow = n0 + c, qn = s_qb[c];
        #pragma unroll
        for (int j = 0; j < 8; ++j) {
            int r0 = hseg * 64 + j * 8;
            unsigned pkw[4];
            #pragma unroll
            for (int h2 = 0; h2 < 4; ++h2) {
                int m_a = m0 + r0 + 2 * h2, m_b = m_a + 1;
                float fa = (m_a == nrow || m_a == qn) ? 0.0f
                         : __expf(Tst[(r0 + 2 * h2)     * LDS + c] * 5.0f);
                float fb = (m_b == nrow || m_b == qn) ? 0.0f
                         : __expf(Tst[(r0 + 2 * h2 + 1) * LDS + c] * 5.0f);
                __half2 hh = __floats2half2_rn(fa, fb);
                pkw[h2] = *(unsigned*)&hh;
            }
            *(uint4*)(g_S + (size_t)nrow * N + m0 + r0) =
                make_uint4(pkw[0], pkw[1], pkw[2], pkw[3]);
        }
    }
}

// ---------------- K3: per-row rank select via bitwise binary search ------------
// one CTA (256 threads) per row; 16 fp16 keys/thread in registers.
// 15 MSB-first bit decisions; count(keys < candidate) is pure-ALU + REDUX +
// one lane-0 atomic per warp per iter + one sync. No histogram, no hot-bin
// serialization. Keys are positive fp16 -> bit-15 always 0 -> 15 iters.
__global__ void __launch_bounds__(256) select_kernel(const int* __restrict__ stage_ptr,
                                                     int N, int rank) {
    __shared__ unsigned s_cnt[15];
    __shared__ float    s_red[8];

    int x = blockIdx.x, tid = threadIdx.x;
    int lane = tid & 31, w = tid >> 5;

    const uint4* row16 = (const uint4*)(g_S + (size_t)x * N);   // 8 fp16 per uint4
    uint4 p0 = row16[tid];
    uint4 p1 = row16[tid + 256];
    unsigned pkv[8] = {p0.x, p0.y, p0.z, p0.w, p1.x, p1.y, p1.z, p1.w};
    unsigned k[16];
    #pragma unroll
    for (int r = 0; r < 8; ++r) {
        k[2 * r]     = pkv[r] & 0xffffu;
        k[2 * r + 1] = pkv[r] >> 16;
    }

    if (tid < 15) s_cnt[tid] = 0;
    int stage = *stage_ptr;
    __syncthreads();

    unsigned t = 0;
    if (stage) {
        #pragma unroll
        for (int b = 14; b >= 0; --b) {
            unsigned cand = t | (1u << b);
            unsigned cnt = 0;
            #pragma unroll
            for (int i = 0; i < 16; ++i) cnt += (k[i] < cand);
            cnt = __reduce_add_sync(0xffffffffu, cnt);
            if (lane == 0) atomicAdd(&s_cnt[b], cnt);
            __syncthreads();
            if (s_cnt[b] <= (unsigned)rank) t = cand;
        }
    }
    // t == exact rank-th smallest fp16 key (or 0 when !stage -> sum all)

    float ssum = 0.0f;
    #pragma unroll
    for (int i = 0; i < 16; ++i)
        if (k[i] >= t) ssum += __half2float(__ushort_as_half((unsigned short)k[i]));

    #pragma unroll
    for (int o = 16; o; o >>= 1) ssum += __shfl_xor_sync(0xffffffffu, ssum, o);
    if (lane == 0) s_red[w] = ssum;
    __syncthreads();
    if (tid == 0) {
        float tot = 0.0f;
        #pragma unroll
        for (int ww = 0; ww < 8; ++ww) tot += s_red[ww];
        float pos = g_pos[x];
        g_loss[x] = -logf(pos / (pos + tot));
    }
}

// ---------------- K4: deterministic mean reduce --------------------------------
__global__ void reduce_kernel(float* __restrict__ out, int N) {
    __shared__ float s_red[8];
    int tid = threadIdx.x;
    float s = 0.0f;
    for (int i = tid; i < N; i += 256) s += g_loss[i];
    int lane = tid & 31, w = tid >> 5;
    #pragma unroll
    for (int o = 16; o; o >>= 1) s += __shfl_xor_sync(0xffffffffu, s, o);
    if (lane == 0) s_red[w] = s;
    __syncthreads();
    if (tid == 0) {
        float tot = 0.0f;
        #pragma unroll
        for (int ww = 0; ww < 8; ++ww) tot += s_red[ww];
        out[0] = tot / (float)N;
    }
}

// ---------------- launch --------------------------------------------------------
extern "C" void kernel_launch(void* const* d_in, const int* in_sizes, int n_in,
                              void* d_out, int out_size) {
    const float* emb   = (const float*)d_in[0];
    const int*   pp    = (const int*)d_in[1];
    const int*   stage = (const int*)d_in[2];

    int N      = in_sizes[0] / D;        // 4096
    int npairs = in_sizes[1] / 2;        // 4096

    build_q_kernel<<<(npairs + 255) / 256, 256>>>(pp, npairs);
    prep_kernel<<<N, D>>>(emb, N);

    int nb   = N >> 7;
    int nblk = nb * (nb + 1) / 2;        // upper triangle
    int smem = 2 * TSZn * 2;             // 69632 bytes (staging 67584 fits inside)
    cudaFuncSetAttribute(gemm_wmma_kernel,
                         cudaFuncAttributeMaxDynamicSharedMemorySize, smem);
    gemm_wmma_kernel<<<nblk, 256, smem>>>(N);

    int rank = (int)(0.8 * (double)(N - 1) + 1e-9);   // 3276 for N=4096
    select_kernel<<<N, 256>>>(stage, N, rank);

    reduce_kernel<<<1, 256>>>((float*)d_out, N);
}

// round 14
// speedup vs baseline: 1.1255x; 1.1255x over previous
#include <cuda_runtime.h>
#include <cuda_bf16.h>
#include <cuda_fp16.h>
#include <mma.h>
#include <math.h>
#include <stdint.h>

using namespace nvcuda;

#define MAXN 4096
#define D    128

// ---------------- scratch (device globals; no allocation allowed) -------------
__device__ __half        g_S[(size_t)MAXN * MAXN]; // exp(sim/tau) in fp16, masked = 0
__device__ __nv_bfloat16 g_hn[MAXN * D];           // normalized hard_neg rows (bf16)
__device__ float         g_pos[MAXN];              // exp(cos(hp_x, hp_qx)/tau)
__device__ float         g_loss[MAXN];
__device__ int           g_q[MAXN];                // positive-pair partner

// ---------------- K0: build partner map ---------------------------------------
__global__ void build_q_kernel(const int* __restrict__ pp, int npairs) {
    int r = blockIdx.x * blockDim.x + threadIdx.x;
    if (r < npairs) g_q[pp[2 * r]] = pp[2 * r + 1];
}

// ---------------- K1: normalized hard_neg rows (bf16) + pos --------------------
__global__ void prep_kernel(const float* __restrict__ emb, int N) {
    int x = blockIdx.x;
    int d = threadIdx.x;
    int qx = g_q[x];
    int fx = N - 1;
    while (fx == x || fx == qx) fx--;   // largest index not in {x, q[x]}

    float a  = emb[(size_t)x  * D + d];
    float b  = emb[(size_t)qx * D + d];
    float pf = emb[(size_t)fx * D + d];
    float h  = 0.5f * (a + pf);

    float v0 = h * h, v1 = a * a, v2 = b * b, v3 = a * b;
    __shared__ float sh[4][4];
    int lane = d & 31, w = d >> 5;
    #pragma unroll
    for (int o = 16; o; o >>= 1) {
        v0 += __shfl_xor_sync(0xffffffffu, v0, o);
        v1 += __shfl_xor_sync(0xffffffffu, v1, o);
        v2 += __shfl_xor_sync(0xffffffffu, v2, o);
        v3 += __shfl_xor_sync(0xffffffffu, v3, o);
    }
    if (lane == 0) { sh[0][w] = v0; sh[1][w] = v1; sh[2][w] = v2; sh[3][w] = v3; }
    __syncthreads();
    float nn = sh[0][0] + sh[0][1] + sh[0][2] + sh[0][3];
    float inv = 1.0f / fmaxf(sqrtf(nn), 1e-8f);
    g_hn[(size_t)x * D + d] = __float2bfloat16(h * inv);

    if (d == 0) {
        float aa = sh[1][0] + sh[1][1] + sh[1][2] + sh[1][3];
        float bb = sh[2][0] + sh[2][1] + sh[2][2] + sh[2][3];
        float ab = sh[3][0] + sh[3][1] + sh[3][2] + sh[3][3];
        float dot = 2.5f * ab - 0.75f * (aa + bb);
        float nxx = 2.25f * aa + 0.25f * bb - 1.5f * ab;
        float nyy = 2.25f * bb + 0.25f * aa - 1.5f * ab;
        float nx = fmaxf(sqrtf(nxx), 1e-8f);
        float ny = fmaxf(sqrtf(nyy), 1e-8f);
        g_pos[x] = expf((dot / (nx * ny)) * 5.0f);
    }
}

// ---------------- K2: WMMA bf16 GEMM + exp + mask (fp16 out, TRIANGLE) ---------
// 128x128 tile per CTA, upper triangle only (528 CTAs), mirror store.
// Full K=128 resident (KP=136 bf16 = 272B stride, ldmatrix conflict-free).
// Inner loop keeps ONE b-fragment live -> no spills at 2 CTAs/SM.
#define KPn 136
#define TSZn (128 * KPn)     // bf16 elements per tile (34816 B)
#define LDS 132              // staging row stride (floats); 528B = 33*16B -> legal

__global__ void __launch_bounds__(256, 2) gemm_wmma_kernel(int N) {
    extern __shared__ char smem[];
    __nv_bfloat16* Ah = (__nv_bfloat16*)smem;
    __nv_bfloat16* Bh = Ah + TSZn;
    float* Tst = (float*)smem;          // epilogue staging 128 x LDS (reuses tiles)
    __shared__ int s_qa[128];           // q[m0 + r]
    __shared__ int s_qb[128];           // q[n0 + c]

    int nb = N >> 7;
    int bid = blockIdx.x;
    int bi = 0, rem = bid;
    while (rem >= nb - bi) { rem -= nb - bi; bi++; }
    int bj = bi + rem;                  // bj >= bi
    int m0 = bi * 128, n0 = bj * 128;

    int tid = threadIdx.x, wid = tid >> 5;
    int wm = wid >> 1, wn = wid & 1;    // warp tile: rows wm*32..+32, cols wn*64..+64

    if (tid < 128)      s_qa[tid]       = g_q[m0 + tid];
    else                s_qb[tid - 128] = g_q[n0 + (tid - 128)];

    wmma::fragment<wmma::accumulator, 16, 16, 16, float> acc[2][4];
    #pragma unroll
    for (int i = 0; i < 2; ++i)
        #pragma unroll
        for (int j = 0; j < 4; ++j) wmma::fill_fragment(acc[i][j], 0.0f);

    // load both full-K tiles (128 rows x 128 bf16 = 16 uint4/row)
    {
        const __nv_bfloat16* srcA = g_hn + (size_t)bi * 128 * D;
        const __nv_bfloat16* srcB = g_hn + (size_t)bj * 128 * D;
        #pragma unroll
        for (int i = tid; i < 2048; i += 256) {
            int row = i >> 4, c8 = i & 15;
            *(uint4*)(Ah + row * KPn + c8 * 8) = *(const uint4*)(srcA + (size_t)row * D + c8 * 8);
            *(uint4*)(Bh + row * KPn + c8 * 8) = *(const uint4*)(srcB + (size_t)row * D + c8 * 8);
        }
    }
    __syncthreads();

    #pragma unroll
    for (int ks = 0; ks < 8; ++ks) {
        wmma::fragment<wmma::matrix_a, 16, 16, 16, __nv_bfloat16, wmma::row_major> a_f[2];
        #pragma unroll
        for (int i = 0; i < 2; ++i)
            wmma::load_matrix_sync(a_f[i], Ah + (wm * 32 + i * 16) * KPn + ks * 16, KPn);
        #pragma unroll
        for (int j = 0; j < 4; ++j) {
            wmma::fragment<wmma::matrix_b, 16, 16, 16, __nv_bfloat16, wmma::col_major> b_f;
            wmma::load_matrix_sync(b_f, Bh + (wn * 64 + j * 16) * KPn + ks * 16, KPn);
            wmma::mma_sync(acc[0][j], a_f[0], b_f, acc[0][j]);
            wmma::mma_sync(acc[1][j], a_f[1], b_f, acc[1][j]);
        }
    }
    __syncthreads();

    // stage raw accumulators to smem (ldm = 132 floats = 528B, multiple of 16B)
    #pragma unroll
    for (int i = 0; i < 2; ++i)
        #pragma unroll
        for (int j = 0; j < 4; ++j)
            wmma::store_matrix_sync(Tst + (wm * 32 + i * 16) * LDS + wn * 64 + j * 16,
                                    acc[i][j], LDS, wmma::mem_row_major);
    __syncthreads();

    // direct store: thread -> 8 consecutive cols of one row; fused mask+exp; STG.128
    {
        int rbase = tid >> 4;            // 0..15
        int c8 = (tid & 15) * 8;         // 0,8,..,120
        #pragma unroll
        for (int p = 0; p < 8; ++p) {
            int r = p * 16 + rbase;
            int m = m0 + r, qm = s_qa[r];
            const float* src = Tst + r * LDS + c8;
            unsigned pkw[4];
            #pragma unroll
            for (int h2 = 0; h2 < 4; ++h2) {
                int n_a = n0 + c8 + 2 * h2, n_b = n_a + 1;
                float fa = (n_a == m || n_a == qm) ? 0.0f : __expf(src[2 * h2]     * 5.0f);
                float fb = (n_b == m || n_b == qm) ? 0.0f : __expf(src[2 * h2 + 1] * 5.0f);
                __half2 hh = __floats2half2_rn(fa, fb);
                pkw[h2] = *(unsigned*)&hh;
            }
            *(uint4*)(g_S + (size_t)m * N + n0 + c8) =
                make_uint4(pkw[0], pkw[1], pkw[2], pkw[3]);
        }
    }
    // mirror store: thread owns staging column c; gathers 8 rows; fused mask+exp
    {
        int c    = tid & 127;
        int hseg = tid >> 7;             // 0/1 -> r halves
        int nrow = n0 + c, qn = s_qb[c];
        #pragma unroll
        for (int j = 0; j < 8; ++j) {
            int r0 = hseg * 64 + j * 8;
            unsigned pkw[4];
            #pragma unroll
            for (int h2 = 0; h2 < 4; ++h2) {
                int m_a = m0 + r0 + 2 * h2, m_b = m_a + 1;
                float fa = (m_a == nrow || m_a == qn) ? 0.0f
                         : __expf(Tst[(r0 + 2 * h2)     * LDS + c] * 5.0f);
                float fb = (m_b == nrow || m_b == qn) ? 0.0f
                         : __expf(Tst[(r0 + 2 * h2 + 1) * LDS + c] * 5.0f);
                __half2 hh = __floats2half2_rn(fa, fb);
                pkw[h2] = *(unsigned*)&hh;
            }
            *(uint4*)(g_S + (size_t)nrow * N + m0 + r0) =
                make_uint4(pkw[0], pkw[1], pkw[2], pkw[3]);
        }
    }
}

// ---------------- K3: radix select, 16 half-warp-private histograms ------------
// Copies are strided 257 words: 257 % 32 == 1, so the two half-warp copies of
// one warp live in DIFFERENT banks (the 256-word stride aliased all copies onto
// the same bank). Same-address conflict degree <= 16. Fold happens in the scan.
#define HCOP   16
#define HSTR   257
#define HTOT   (HCOP * HSTR)   // 4112 words

__device__ __forceinline__ void locate_bin_hw(unsigned* hist, unsigned k,
                                              unsigned* s_warp, int* s_bin, int* s_krem) {
    int tid = threadIdx.x;
    unsigned local = 0;
    #pragma unroll
    for (int i = 0; i < HCOP; ++i) local += hist[tid + HSTR * i];
    unsigned inc = local;
    int lane = tid & 31, w = tid >> 5;
    #pragma unroll
    for (int o = 1; o < 32; o <<= 1) {
        unsigned t = __shfl_up_sync(0xffffffffu, inc, o);
        if (lane >= o) inc += t;
    }
    if (lane == 31) s_warp[w] = inc;
    __syncthreads();
    unsigned woff = 0;
    for (int ww = 0; ww < w; ++ww) woff += s_warp[ww];
    unsigned excl = woff + inc - local;
    if (excl <= k && k < excl + local) { *s_bin = tid; *s_krem = (int)(k - excl); }
    __syncthreads();
}

__global__ void __launch_bounds__(256) select_kernel(const int* __restrict__ stage_ptr,
                                                     int N, int rank) {
    __shared__ unsigned hist[HTOT];
    __shared__ unsigned s_warp[8];
    __shared__ int      s_bin, s_krem;
    __shared__ float    s_red[8];

    int x = blockIdx.x, tid = threadIdx.x;
    const uint4* row16 = (const uint4*)(g_S + (size_t)x * N);   // 8 fp16 per uint4
    uint4 p0 = row16[tid];
    uint4 p1 = row16[tid + 256];
    unsigned pk[8] = {p0.x, p0.y, p0.z, p0.w, p1.x, p1.y, p1.z, p1.w};

    int stage = *stage_ptr;
    float ssum = 0.0f;
    unsigned hbase = (unsigned)(tid >> 4) * HSTR;   // half-warp-private copy

    if (stage) {
        // ---- L0: fp16 bits [15:8] ----
        for (int i = tid; i < HTOT; i += 256) hist[i] = 0;
        __syncthreads();
        #pragma unroll
        for (int r = 0; r < 8; ++r) {
            atomicAdd(&hist[hbase + ((pk[r] >> 8)  & 0xffu)], 1u);
            atomicAdd(&hist[hbase + ((pk[r] >> 24) & 0xffu)], 1u);
        }
        __syncthreads();
        locate_bin_hw(hist, (unsigned)rank, s_warp, &s_bin, &s_krem);
        unsigned b0 = (unsigned)s_bin;
        unsigned k1 = (unsigned)s_krem;
        __syncthreads();

        // ---- L1: fp16 bits [7:0] within bin b0 ----
        for (int i = tid; i < HTOT; i += 256) hist[i] = 0;
        __syncthreads();
        #pragma unroll
        for (int r = 0; r < 8; ++r) {
            unsigned lo = pk[r] & 0xffffu, hi = pk[r] >> 16;
            if ((lo >> 8) == b0) atomicAdd(&hist[hbase + (lo & 0xffu)], 1u);
            if ((hi >> 8) == b0) atomicAdd(&hist[hbase + (hi & 0xffu)], 1u);
        }
        __syncthreads();
        locate_bin_hw(hist, k1, s_warp, &s_bin, &s_krem);
        unsigned tbits = (b0 << 8) | (unsigned)s_bin;   // exact rank-th fp16 value

        #pragma unroll
        for (int r = 0; r < 8; ++r) {
            unsigned lo = pk[r] & 0xffffu, hi = pk[r] >> 16;
            if (lo >= tbits) ssum += __half2float(__ushort_as_half((unsigned short)lo));
            if (hi >= tbits) ssum += __half2float(__ushort_as_half((unsigned short)hi));
        }
    } else {
        #pragma unroll
        for (int r = 0; r < 8; ++r) {
            ssum += __half2float(__ushort_as_half((unsigned short)(pk[r] & 0xffffu)));
            ssum += __half2float(__ushort_as_half((unsigned short)(pk[r] >> 16)));
        }
    }

    int lane = tid & 31, w = tid >> 5;
    #pragma unroll
    for (int o = 16; o; o >>= 1) ssum += __shfl_xor_sync(0xffffffffu, ssum, o);
    if (lane == 0) s_red[w] = ssum;
    __syncthreads();
    if (tid == 0) {
        float tot = 0.0f;
        #pragma unroll
        for (int ww = 0; ww < 8; ++ww) tot += s_red[ww];
        float pos = g_pos[x];
        g_loss[x] = -logf(pos / (pos + tot));
    }
}

// ---------------- K4: deterministic mean reduce --------------------------------
__global__ void reduce_kernel(float* __restrict__ out, int N) {
    __shared__ float s_red[8];
    int tid = threadIdx.x;
    float s = 0.0f;
    for (int i = tid; i < N; i += 256) s += g_loss[i];
    int lane = tid & 31, w = tid >> 5;
    #pragma unroll
    for (int o = 16; o; o >>= 1) s += __shfl_xor_sync(0xffffffffu, s, o);
    if (lane == 0) s_red[w] = s;
    __syncthreads();
    if (tid == 0) {
        float tot = 0.0f;
        #pragma unroll
        for (int ww = 0; ww < 8; ++ww) tot += s_red[ww];
        out[0] = tot / (float)N;
    }
}

// ---------------- launch --------------------------------------------------------
extern "C" void kernel_launch(void* const* d_in, const int* in_sizes, int n_in,
                              void* d_out, int out_size) {
    const float* emb   = (const float*)d_in[0];
    const int*   pp    = (const int*)d_in[1];
    const int*   stage = (const int*)d_in[2];

    int N      = in_sizes[0] / D;        // 4096
    int npairs = in_sizes[1] / 2;        // 4096

    build_q_kernel<<<(npairs + 255) / 256, 256>>>(pp, npairs);
    prep_kernel<<<N, D>>>(emb, N);

    int nb   = N >> 7;
    int nblk = nb * (nb + 1) / 2;        // upper triangle
    int smem = 2 * TSZn * 2;             // 69632 bytes (staging 67584 fits inside)
    cudaFuncSetAttribute(gemm_wmma_kernel,
                         cudaFuncAttributeMaxDynamicSharedMemorySize, smem);
    gemm_wmma_kernel<<<nblk, 256, smem>>>(N);

    int rank = (int)(0.8 * (double)(N - 1) + 1e-9);   // 3276 for N=4096
    select_kernel<<<N, 256>>>(stage, N, rank);

    reduce_kernel<<<1, 256>>>((float*)d_out, N);
}

// round 15
// speedup vs baseline: 1.1450x; 1.0173x over previous
#include <cuda_runtime.h>
#include <cuda_bf16.h>
#include <cuda_fp16.h>
#include <mma.h>
#include <math.h>
#include <stdint.h>

using namespace nvcuda;

#define MAXN 4096
#define D    128

// ---------------- scratch (device globals; no allocation allowed) -------------
__device__ __half        g_S[(size_t)MAXN * MAXN]; // exp(sim/tau) in fp16, masked = 0
__device__ __nv_bfloat16 g_hn[MAXN * D];           // normalized hard_neg rows (bf16)
__device__ float         g_pos[MAXN];              // exp(cos(hp_x, hp_qx)/tau)
__device__ float         g_loss[MAXN];
__device__ int           g_q[MAXN];                // positive-pair partner

// ---------------- K0: build partner map ---------------------------------------
__global__ void build_q_kernel(const int* __restrict__ pp, int npairs) {
    int r = blockIdx.x * blockDim.x + threadIdx.x;
    if (r < npairs) g_q[pp[2 * r]] = pp[2 * r + 1];
}

// ---------------- K1: normalized hard_neg rows (bf16) + pos --------------------
__global__ void prep_kernel(const float* __restrict__ emb, int N) {
    int x = blockIdx.x;
    int d = threadIdx.x;
    int qx = g_q[x];
    int fx = N - 1;
    while (fx == x || fx == qx) fx--;   // largest index not in {x, q[x]}

    float a  = emb[(size_t)x  * D + d];
    float b  = emb[(size_t)qx * D + d];
    float pf = emb[(size_t)fx * D + d];
    float h  = 0.5f * (a + pf);

    float v0 = h * h, v1 = a * a, v2 = b * b, v3 = a * b;
    __shared__ float sh[4][4];
    int lane = d & 31, w = d >> 5;
    #pragma unroll
    for (int o = 16; o; o >>= 1) {
        v0 += __shfl_xor_sync(0xffffffffu, v0, o);
        v1 += __shfl_xor_sync(0xffffffffu, v1, o);
        v2 += __shfl_xor_sync(0xffffffffu, v2, o);
        v3 += __shfl_xor_sync(0xffffffffu, v3, o);
    }
    if (lane == 0) { sh[0][w] = v0; sh[1][w] = v1; sh[2][w] = v2; sh[3][w] = v3; }
    __syncthreads();
    float nn = sh[0][0] + sh[0][1] + sh[0][2] + sh[0][3];
    float inv = 1.0f / fmaxf(sqrtf(nn), 1e-8f);
    g_hn[(size_t)x * D + d] = __float2bfloat16(h * inv);

    if (d == 0) {
        float aa = sh[1][0] + sh[1][1] + sh[1][2] + sh[1][3];
        float bb = sh[2][0] + sh[2][1] + sh[2][2] + sh[2][3];
        float ab = sh[3][0] + sh[3][1] + sh[3][2] + sh[3][3];
        float dot = 2.5f * ab - 0.75f * (aa + bb);
        float nxx = 2.25f * aa + 0.25f * bb - 1.5f * ab;
        float nyy = 2.25f * bb + 0.25f * aa - 1.5f * ab;
        float nx = fmaxf(sqrtf(nxx), 1e-8f);
        float ny = fmaxf(sqrtf(nyy), 1e-8f);
        g_pos[x] = expf((dot / (nx * ny)) * 5.0f);
    }
}

// ---------------- K2: WMMA bf16 GEMM + exp + mask (fp16 out, TRIANGLE) ---------
// 128x128 tile per CTA, upper triangle only (528 CTAs), mirror store.
// Full K=128 resident (KP=136 bf16 = 272B stride, ldmatrix conflict-free).
#define KPn 136
#define TSZn (128 * KPn)     // bf16 elements per tile (34816 B)
#define LDS 132              // staging row stride (floats); 528B = 33*16B -> legal

__global__ void __launch_bounds__(256, 2) gemm_wmma_kernel(int N) {
    extern __shared__ char smem[];
    __nv_bfloat16* Ah = (__nv_bfloat16*)smem;
    __nv_bfloat16* Bh = Ah + TSZn;
    float* Tst = (float*)smem;          // epilogue staging 128 x LDS (reuses tiles)
    __shared__ int s_qa[128];           // q[m0 + r]
    __shared__ int s_qb[128];           // q[n0 + c]

    int nb = N >> 7;
    int bid = blockIdx.x;
    int bi = 0, rem = bid;
    while (rem >= nb - bi) { rem -= nb - bi; bi++; }
    int bj = bi + rem;                  // bj >= bi
    int m0 = bi * 128, n0 = bj * 128;

    int tid = threadIdx.x, wid = tid >> 5;
    int wm = wid >> 1, wn = wid & 1;    // warp tile: rows wm*32..+32, cols wn*64..+64

    if (tid < 128)      s_qa[tid]       = g_q[m0 + tid];
    else                s_qb[tid - 128] = g_q[n0 + (tid - 128)];

    wmma::fragment<wmma::accumulator, 16, 16, 16, float> acc[2][4];
    #pragma unroll
    for (int i = 0; i < 2; ++i)
        #pragma unroll
        for (int j = 0; j < 4; ++j) wmma::fill_fragment(acc[i][j], 0.0f);

    // load both full-K tiles (128 rows x 128 bf16 = 16 uint4/row)
    {
        const __nv_bfloat16* srcA = g_hn + (size_t)bi * 128 * D;
        const __nv_bfloat16* srcB = g_hn + (size_t)bj * 128 * D;
        #pragma unroll
        for (int i = tid; i < 2048; i += 256) {
            int row = i >> 4, c8 = i & 15;
            *(uint4*)(Ah + row * KPn + c8 * 8) = *(const uint4*)(srcA + (size_t)row * D + c8 * 8);
            *(uint4*)(Bh + row * KPn + c8 * 8) = *(const uint4*)(srcB + (size_t)row * D + c8 * 8);
        }
    }
    __syncthreads();

    #pragma unroll
    for (int ks = 0; ks < 8; ++ks) {
        wmma::fragment<wmma::matrix_a, 16, 16, 16, __nv_bfloat16, wmma::row_major> a_f[2];
        #pragma unroll
        for (int i = 0; i < 2; ++i)
            wmma::load_matrix_sync(a_f[i], Ah + (wm * 32 + i * 16) * KPn + ks * 16, KPn);
        #pragma unroll
        for (int j = 0; j < 4; ++j) {
            wmma::fragment<wmma::matrix_b, 16, 16, 16, __nv_bfloat16, wmma::col_major> b_f;
            wmma::load_matrix_sync(b_f, Bh + (wn * 64 + j * 16) * KPn + ks * 16, KPn);
            wmma::mma_sync(acc[0][j], a_f[0], b_f, acc[0][j]);
            wmma::mma_sync(acc[1][j], a_f[1], b_f, acc[1][j]);
        }
    }
    __syncthreads();

    // stage raw accumulators to smem (ldm = 132 floats = 528B, multiple of 16B)
    #pragma unroll
    for (int i = 0; i < 2; ++i)
        #pragma unroll
        for (int j = 0; j < 4; ++j)
            wmma::store_matrix_sync(Tst + (wm * 32 + i * 16) * LDS + wn * 64 + j * 16,
                                    acc[i][j], LDS, wmma::mem_row_major);
    __syncthreads();

    // direct store: thread -> 8 consecutive cols of one row; fused mask+exp; STG.128
    {
        int rbase = tid >> 4;            // 0..15
        int c8 = (tid & 15) * 8;         // 0,8,..,120
        #pragma unroll
        for (int p = 0; p < 8; ++p) {
            int r = p * 16 + rbase;
            int m = m0 + r, qm = s_qa[r];
            const float* src = Tst + r * LDS + c8;
            unsigned pkw[4];
            #pragma unroll
            for (int h2 = 0; h2 < 4; ++h2) {
                int n_a = n0 + c8 + 2 * h2, n_b = n_a + 1;
                float fa = (n_a == m || n_a == qm) ? 0.0f : __expf(src[2 * h2]     * 5.0f);
                float fb = (n_b == m || n_b == qm) ? 0.0f : __expf(src[2 * h2 + 1] * 5.0f);
                __half2 hh = __floats2half2_rn(fa, fb);
                pkw[h2] = *(unsigned*)&hh;
            }
            *(uint4*)(g_S + (size_t)m * N + n0 + c8) =
                make_uint4(pkw[0], pkw[1], pkw[2], pkw[3]);
        }
    }
    // mirror store: thread owns staging column c; gathers 8 rows; fused mask+exp
    {
        int c    = tid & 127;
        int hseg = tid >> 7;             // 0/1 -> r halves
        int nrow = n0 + c, qn = s_qb[c];
        #pragma unroll
        for (int j = 0; j < 8; ++j) {
            int r0 = hseg * 64 + j * 8;
            unsigned pkw[4];
            #pragma unroll
            for (int h2 = 0; h2 < 4; ++h2) {
                int m_a = m0 + r0 + 2 * h2, m_b = m_a + 1;
                float fa = (m_a == nrow || m_a == qn) ? 0.0f
                         : __expf(Tst[(r0 + 2 * h2)     * LDS + c] * 5.0f);
                float fb = (m_b == nrow || m_b == qn) ? 0.0f
                         : __expf(Tst[(r0 + 2 * h2 + 1) * LDS + c] * 5.0f);
                __half2 hh = __floats2half2_rn(fa, fb);
                pkw[h2] = *(unsigned*)&hh;
            }
            *(uint4*)(g_S + (size_t)nrow * N + m0 + r0) =
                make_uint4(pkw[0], pkw[1], pkw[2], pkw[3]);
        }
    }
}

// ---------------- K3 helper: scan 8 privatized histogram copies ----------------
__device__ __forceinline__ void locate_bin256x8(unsigned* hist, unsigned k,
                                                unsigned* s_warp, int* s_bin, int* s_krem) {
    int tid = threadIdx.x;
    unsigned local = 0;
    #pragma unroll
    for (int i = 0; i < 8; ++i) local += hist[tid + 256 * i];
    unsigned inc = local;
    int lane = tid & 31, w = tid >> 5;
    #pragma unroll
    for (int o = 1; o < 32; o <<= 1) {
        unsigned t = __shfl_up_sync(0xffffffffu, inc, o);
        if (lane >= o) inc += t;
    }
    if (lane == 31) s_warp[w] = inc;
    __syncthreads();
    unsigned woff = 0;
    for (int ww = 0; ww < w; ++ww) woff += s_warp[ww];
    unsigned excl = woff + inc - local;
    if (excl <= k && k < excl + local) { *s_bin = tid; *s_krem = (int)(k - excl); }
    __syncthreads();
}

// ---------------- K3: per-row exact radix select + thresholded sum (fp16) ------
// R11 structure (measured best) + in-thread atomic aggregation: values are
// heavily concentrated, so neighboring keys usually share a bin -> combine
// equal-bin increments (+2 / +4) before touching shared memory.
__global__ void __launch_bounds__(256) select_kernel(const int* __restrict__ stage_ptr,
                                                     int N, int rank) {
    __shared__ unsigned hist[2048];     // 8 warp-private copies of 256 bins
    __shared__ unsigned s_warp[8];
    __shared__ int      s_bin, s_krem;
    __shared__ float    s_red[8];

    int x = blockIdx.x, tid = threadIdx.x, wid = tid >> 5;
    const uint4* row16 = (const uint4*)(g_S + (size_t)x * N);   // 8 fp16 per uint4
    uint4 p0 = row16[tid];
    uint4 p1 = row16[tid + 256];
    unsigned pk[8] = {p0.x, p0.y, p0.z, p0.w, p1.x, p1.y, p1.z, p1.w};

    int stage = *stage_ptr;
    float ssum = 0.0f;
    unsigned hbase = (unsigned)wid << 8;

    if (stage) {
        // ---- L0: fp16 bits [15:8], aggregated increments ----
        #pragma unroll
        for (int i = 0; i < 8; ++i) hist[tid + 256 * i] = 0;
        __syncthreads();
        #pragma unroll
        for (int r = 0; r < 8; r += 2) {
            unsigned b00 = (pk[r]     >> 8)  & 0xffu;
            unsigned b01 =  pk[r]     >> 24;
            unsigned b10 = (pk[r + 1] >> 8)  & 0xffu;
            unsigned b11 =  pk[r + 1] >> 24;
            if (b00 == b01 && b00 == b10 && b00 == b11) {
                atomicAdd(&hist[hbase + b00], 4u);
            } else {
                if (b00 == b01) atomicAdd(&hist[hbase + b00], 2u);
                else { atomicAdd(&hist[hbase + b00], 1u); atomicAdd(&hist[hbase + b01], 1u); }
                if (b10 == b11) atomicAdd(&hist[hbase + b10], 2u);
                else { atomicAdd(&hist[hbase + b10], 1u); atomicAdd(&hist[hbase + b11], 1u); }
            }
        }
        __syncthreads();
        locate_bin256x8(hist, (unsigned)rank, s_warp, &s_bin, &s_krem);
        unsigned b0 = (unsigned)s_bin;
        unsigned k1 = (unsigned)s_krem;
        __syncthreads();

        // ---- L1: fp16 bits [7:0] within bin b0, aggregated increments ----
        #pragma unroll
        for (int i = 0; i < 8; ++i) hist[tid + 256 * i] = 0;
        __syncthreads();
        #pragma unroll
        for (int r = 0; r < 8; ++r) {
            unsigned lo = pk[r] & 0xffffu, hi = pk[r] >> 16;
            bool il = (lo >> 8) == b0, ih = (hi >> 8) == b0;
            unsigned bl = lo & 0xffu, bh = hi & 0xffu;
            if (il && ih && bl == bh) {
                atomicAdd(&hist[hbase + bl], 2u);
            } else {
                if (il) atomicAdd(&hist[hbase + bl], 1u);
                if (ih) atomicAdd(&hist[hbase + bh], 1u);
            }
        }
        __syncthreads();
        locate_bin256x8(hist, k1, s_warp, &s_bin, &s_krem);
        unsigned tbits = (b0 << 8) | (unsigned)s_bin;   // exact rank-th fp16 value

        #pragma unroll
        for (int r = 0; r < 8; ++r) {
            unsigned lo = pk[r] & 0xffffu, hi = pk[r] >> 16;
            if (lo >= tbits) ssum += __half2float(__ushort_as_half((unsigned short)lo));
            if (hi >= tbits) ssum += __half2float(__ushort_as_half((unsigned short)hi));
        }
    } else {
        #pragma unroll
        for (int r = 0; r < 8; ++r) {
            ssum += __half2float(__ushort_as_half((unsigned short)(pk[r] & 0xffffu)));
            ssum += __half2float(__ushort_as_half((unsigned short)(pk[r] >> 16)));
        }
    }

    int lane = tid & 31, w = tid >> 5;
    #pragma unroll
    for (int o = 16; o; o >>= 1) ssum += __shfl_xor_sync(0xffffffffu, ssum, o);
    if (lane == 0) s_red[w] = ssum;
    __syncthreads();
    if (tid == 0) {
        float tot = 0.0f;
        #pragma unroll
        for (int ww = 0; ww < 8; ++ww) tot += s_red[ww];
        float pos = g_pos[x];
        g_loss[x] = -logf(pos / (pos + tot));
    }
}

// ---------------- K4: deterministic mean reduce --------------------------------
__global__ void reduce_kernel(float* __restrict__ out, int N) {
    __shared__ float s_red[8];
    int tid = threadIdx.x;
    float s = 0.0f;
    for (int i = tid; i < N; i += 256) s += g_loss[i];
    int lane = tid & 31, w = tid >> 5;
    #pragma unroll
    for (int o = 16; o; o >>= 1) s += __shfl_xor_sync(0xffffffffu, s, o);
    if (lane == 0) s_red[w] = s;
    __syncthreads();
    if (tid == 0) {
        float tot = 0.0f;
        #pragma unroll
        for (int ww = 0; ww < 8; ++ww) tot += s_red[ww];
        out[0] = tot / (float)N;
    }
}

// ---------------- launch --------------------------------------------------------
extern "C" void kernel_launch(void* const* d_in, const int* in_sizes, int n_in,
                              void* d_out, int out_size) {
    const float* emb   = (const float*)d_in[0];
    const int*   pp    = (const int*)d_in[1];
    const int*   stage = (const int*)d_in[2];

    int N      = in_sizes[0] / D;        // 4096
    int npairs = in_sizes[1] / 2;        // 4096

    build_q_kernel<<<(npairs + 255) / 256, 256>>>(pp, npairs);
    prep_kernel<<<N, D>>>(emb, N);

    int nb   = N >> 7;
    int nblk = nb * (nb + 1) / 2;        // upper triangle
    int smem = 2 * TSZn * 2;             // 69632 bytes (staging 67584 fits inside)
    cudaFuncSetAttribute(gemm_wmma_kernel,
                         cudaFuncAttributeMaxDynamicSharedMemorySize, smem);
    gemm_wmma_kernel<<<nblk, 256, smem>>>(N);

    int rank = (int)(0.8 * (double)(N - 1) + 1e-9);   // 3276 for N=4096
    select_kernel<<<N, 256>>>(stage, N, rank);

    reduce_kernel<<<1, 256>>>((float*)d_out, N);
}